// round 1
// baseline (speedup 1.0000x reference)
#include <cuda_runtime.h>
#include <math.h>

#define Bn 4
#define CIN 128
#define Np 4096
#define Hd 128
#define COUT 256
#define Kn 16
#define SEH 64
#define NCHUNK 16
#define EPSB 1e-5f
#define NT 32   // 4096/128 tiles

// ---------------- scratch (static __device__, no allocations) ----------------
__device__ float g_sq[Bn * Np];
__device__ float g_d2[(size_t)Bn * Np * Np];        // 256 MiB
__device__ int   g_idx[Bn * Np * Kn];
__device__ float g_W1T[CIN * Hd];                   // [c][h]
__device__ float g_WCT[CIN * Hd];                   // [c][h]
__device__ float g_beff[Hd];
__device__ float g_WfuseT[Hd * COUT];               // [h][o]
__device__ float g_b2[COUT];
__device__ float g_WresT[CIN * COUT];               // [c][o]
__device__ float g_b3[COUT];
__device__ float g_A[(size_t)Bn * Np * Hd];         // x_t @ W1eff^T
__device__ float g_C[(size_t)Bn * Np * Hd];         // x_t @ WCeff^T + beff
__device__ float g_outpre[(size_t)Bn * Np * COUT];  // post fuse+BN2+relu, pre-SE
__device__ float g_se[Bn * NCHUNK * COUT];

// ---------------- prep: fold all BN into weights ----------------
__global__ void prep_kernel(const float* __restrict__ W_edge,
                            const float* __restrict__ g1, const float* __restrict__ b1,
                            const float* __restrict__ m1, const float* __restrict__ v1,
                            const float* __restrict__ W_fuse,
                            const float* __restrict__ g2, const float* __restrict__ b2,
                            const float* __restrict__ m2, const float* __restrict__ v2,
                            const float* __restrict__ W_res,
                            const float* __restrict__ g3, const float* __restrict__ b3,
                            const float* __restrict__ m3, const float* __restrict__ v3) {
    int i = blockIdx.x * blockDim.x + threadIdx.x;
    int stride = gridDim.x * blockDim.x;
    for (int t = i; t < CIN * Hd; t += stride) {
        int h = t % Hd, c = t / Hd;
        float s = g1[h] * rsqrtf(v1[h] + EPSB);
        float w1 = W_edge[h * (2 * CIN) + c];
        float w2 = W_edge[h * (2 * CIN) + CIN + c];
        g_W1T[t] = w1 * s;
        g_WCT[t] = (w2 - w1) * s;
    }
    for (int h = i; h < Hd; h += stride) {
        float s = g1[h] * rsqrtf(v1[h] + EPSB);
        g_beff[h] = b1[h] - m1[h] * s;
    }
    for (int t = i; t < Hd * COUT; t += stride) {
        int o = t % COUT, h = t / COUT;
        float s = g2[o] * rsqrtf(v2[o] + EPSB);
        g_WfuseT[t] = W_fuse[o * Hd + h] * s;
    }
    for (int o = i; o < COUT; o += stride) {
        float s2 = g2[o] * rsqrtf(v2[o] + EPSB);
        g_b2[o] = b2[o] - m2[o] * s2;
        float s3 = g3[o] * rsqrtf(v3[o] + EPSB);
        g_b3[o] = b3[o] - m3[o] * s3;
    }
    for (int t = i; t < CIN * COUT; t += stride) {
        int o = t % COUT, c = t / COUT;
        float s3 = g3[o] * rsqrtf(v3[o] + EPSB);
        g_WresT[t] = W_res[o * CIN + c] * s3;
    }
}

// ---------------- squared norms ----------------
__global__ void sq_kernel(const float* __restrict__ x) {
    int b = blockIdx.y;
    int n = blockIdx.x * 256 + threadIdx.x;
    const float* xb = x + (size_t)b * CIN * Np;
    float s = 0.f;
    for (int c = 0; c < CIN; c++) {
        float v = xb[(size_t)c * Np + n];
        s = fmaf(v, v, s);
    }
    g_sq[b * Np + n] = s;
}

// ---------------- symmetric d2 GEMM: upper-triangle 128x128 tiles ----------------
__global__ __launch_bounds__(256) void d2_kernel(const float* __restrict__ x) {
    int b = blockIdx.y;
    // map linear tile -> (ti, tj) with ti <= tj
    int ti = 0, rem = blockIdx.x;
    while (rem >= NT - ti) { rem -= NT - ti; ti++; }
    int tj = ti + rem;
    int i0 = ti * 128, j0 = tj * 128;

    const float* xb = x + (size_t)b * CIN * Np;
    __shared__ float As[8][128];
    __shared__ float Bs[8][128];
    float acc[8][8];
#pragma unroll
    for (int a = 0; a < 8; a++)
#pragma unroll
        for (int c = 0; c < 8; c++) acc[a][c] = 0.f;

    int tid = threadIdx.x;
    int lx = tid % 16, ly = tid / 16;
    int loadc = tid / 32, loadi = (tid % 32) * 4;

    for (int c0 = 0; c0 < CIN; c0 += 8) {
        const float* rowp = xb + (size_t)(c0 + loadc) * Np;
        *(float4*)&As[loadc][loadi] = *(const float4*)(rowp + i0 + loadi);
        *(float4*)&Bs[loadc][loadi] = *(const float4*)(rowp + j0 + loadi);
        __syncthreads();
#pragma unroll
        for (int k = 0; k < 8; k++) {
            float ar[8], br[8];
#pragma unroll
            for (int a = 0; a < 8; a++) ar[a] = As[k][ly + 16 * a];
#pragma unroll
            for (int c = 0; c < 8; c++) br[c] = Bs[k][lx + 16 * c];
#pragma unroll
            for (int a = 0; a < 8; a++)
#pragma unroll
                for (int c = 0; c < 8; c++) acc[a][c] = fmaf(ar[a], br[c], acc[a][c]);
        }
        __syncthreads();
    }
    // epilogue: d2 = sq_i + sq_j - 2*dot (upper triangle tile only)
    float sqi[8], sqj[8];
#pragma unroll
    for (int a = 0; a < 8; a++) sqi[a] = g_sq[b * Np + i0 + ly + 16 * a];
#pragma unroll
    for (int c = 0; c < 8; c++) sqj[c] = g_sq[b * Np + j0 + lx + 16 * c];
    float* d2b = g_d2 + (size_t)b * Np * Np;
#pragma unroll
    for (int a = 0; a < 8; a++) {
        int ii = i0 + ly + 16 * a;
#pragma unroll
        for (int c = 0; c < 8; c++) {
            int jj = j0 + lx + 16 * c;
            d2b[(size_t)ii * Np + jj] = sqi[a] + sqj[c] - 2.f * acc[a][c];
        }
    }
}

// ---------------- mirror upper triangle to lower ----------------
__global__ void tr_kernel() {
    int b = blockIdx.z;
    int tI = blockIdx.y, tJ = blockIdx.x;
    if (tJ <= tI) return;
    __shared__ float tile[32][33];
    float* d2b = g_d2 + (size_t)b * Np * Np;
    int jx = tJ * 32 + threadIdx.x;
    int iy = tI * 32 + threadIdx.y;
#pragma unroll
    for (int r = 0; r < 4; r++)
        tile[threadIdx.y + 8 * r][threadIdx.x] = d2b[(size_t)(iy + 8 * r) * Np + jx];
    __syncthreads();
    int ix = tI * 32 + threadIdx.x;
    int jy = tJ * 32 + threadIdx.y;
#pragma unroll
    for (int r = 0; r < 4; r++)
        d2b[(size_t)(jy + 8 * r) * Np + ix] = tile[threadIdx.x][threadIdx.y + 8 * r];
}

// ---------------- top-16 smallest per row ----------------
__global__ __launch_bounds__(128) void topk_kernel() {
    int b = blockIdx.y, n = blockIdx.x;
    __shared__ float v[Np];
    __shared__ float rv[128];
    __shared__ int   ri[128];
    const float* row = g_d2 + ((size_t)b * Np + n) * Np;
    int tid = threadIdx.x;
    for (int m = tid; m < Np; m += 128) v[m] = row[m];
    __syncthreads();
    int* outp = g_idx + ((b * Np + n) * Kn);
    for (int it = 0; it < Kn; it++) {
        float best = INFINITY; int bi = 0x7fffffff;
        for (int m = tid; m < Np; m += 128) {
            float val = v[m];
            if (val < best) { best = val; bi = m; }
        }
        rv[tid] = best; ri[tid] = bi;
        __syncthreads();
        for (int s = 64; s > 0; s >>= 1) {
            if (tid < s) {
                float ov = rv[tid + s]; int oi = ri[tid + s];
                if (ov < rv[tid] || (ov == rv[tid] && oi < ri[tid])) { rv[tid] = ov; ri[tid] = oi; }
            }
            __syncthreads();
        }
        if (tid == 0) { outp[it] = ri[0]; v[ri[0]] = INFINITY; }
        __syncthreads();
    }
}

// ---------------- A/C projection GEMMs (128x128 out tile) ----------------
__global__ __launch_bounds__(256) void ac_gemm(const float* __restrict__ x) {
    int b = blockIdx.y;
    int n0 = blockIdx.x * 128;
    int which = blockIdx.z;
    const float* WT = which ? g_WCT : g_W1T;  // [c][h], h contiguous
    const float* xb = x + (size_t)b * CIN * Np;
    __shared__ float As[8][128];
    __shared__ float Bs[8][128];
    float acc[8][8];
#pragma unroll
    for (int a = 0; a < 8; a++)
#pragma unroll
        for (int c = 0; c < 8; c++) acc[a][c] = 0.f;
    int tid = threadIdx.x;
    int lx = tid % 16, ly = tid / 16;
    int loadc = tid / 32, loadi = (tid % 32) * 4;
    for (int c0 = 0; c0 < CIN; c0 += 8) {
        *(float4*)&As[loadc][loadi] = *(const float4*)(xb + (size_t)(c0 + loadc) * Np + n0 + loadi);
        *(float4*)&Bs[loadc][loadi] = *(const float4*)(WT + (size_t)(c0 + loadc) * Hd + loadi);
        __syncthreads();
#pragma unroll
        for (int k = 0; k < 8; k++) {
            float ar[8], br[8];
#pragma unroll
            for (int a = 0; a < 8; a++) ar[a] = As[k][ly + 16 * a];
#pragma unroll
            for (int c = 0; c < 8; c++) br[c] = Bs[k][lx + 16 * c];
#pragma unroll
            for (int a = 0; a < 8; a++)
#pragma unroll
                for (int c = 0; c < 8; c++) acc[a][c] = fmaf(ar[a], br[c], acc[a][c]);
        }
        __syncthreads();
    }
    float* outb = which ? g_C : g_A;
#pragma unroll
    for (int a = 0; a < 8; a++) {
        int n = n0 + ly + 16 * a;
#pragma unroll
        for (int c = 0; c < 8; c++) {
            int h = lx + 16 * c;
            float val = acc[a][c];
            if (which) val += g_beff[h];
            outb[((size_t)b * Np + n) * Hd + h] = val;
        }
    }
}

// ---------------- attention + aggregate + fuse (per query) ----------------
__global__ __launch_bounds__(128) void attn_kernel(const float* __restrict__ w_att) {
    int b = blockIdx.y, n = blockIdx.x;
    int tid = threadIdx.x;  // == h channel, 128
    __shared__ float shp[4][Kn];
    __shared__ float tk[Kn];
    __shared__ float aggs[Hd];
    const int* id = g_idx + ((b * Np + n) * Kn);
    const float* Ab = g_A + (size_t)b * Np * Hd;
    float Cc = g_C[((size_t)b * Np + n) * Hd + tid];
    float hk[Kn];
#pragma unroll
    for (int k = 0; k < Kn; k++) {
        int j = id[k];
        hk[k] = fmaxf(Ab[(size_t)j * Hd + tid] + Cc, 0.f);
    }
    float wa = w_att[tid];
    int lane = tid & 31, w = tid >> 5;
#pragma unroll
    for (int k = 0; k < Kn; k++) {
        float p = hk[k] * wa;
#pragma unroll
        for (int off = 16; off > 0; off >>= 1) p += __shfl_down_sync(0xffffffffu, p, off);
        if (lane == 0) shp[w][k] = p;
    }
    __syncthreads();
    if (tid < Kn) tk[tid] = shp[0][tid] + shp[1][tid] + shp[2][tid] + shp[3][tid];
    __syncthreads();
    // softmax (redundant per thread)
    float mx = -INFINITY;
#pragma unroll
    for (int k = 0; k < Kn; k++) mx = fmaxf(mx, tk[k]);
    float e[Kn]; float ssum = 0.f;
#pragma unroll
    for (int k = 0; k < Kn; k++) { e[k] = __expf(tk[k] - mx); ssum += e[k]; }
    float inv = 1.f / ssum;
    float agg = 0.f;
#pragma unroll
    for (int k = 0; k < Kn; k++) agg = fmaf(e[k], hk[k], agg);
    agg *= inv;
    aggs[tid] = agg;
    __syncthreads();
    // fuse conv1d: 128 -> 256 (two outputs per thread)
    float o0 = g_b2[tid], o1 = g_b2[tid + 128];
#pragma unroll 8
    for (int h = 0; h < Hd; h++) {
        float av = aggs[h];
        o0 = fmaf(av, g_WfuseT[h * COUT + tid], o0);
        o1 = fmaf(av, g_WfuseT[h * COUT + tid + 128], o1);
    }
    float* op = g_outpre + ((size_t)b * Np + n) * COUT;
    op[tid]       = fmaxf(o0, 0.f);
    op[tid + 128] = fmaxf(o1, 0.f);
}

// ---------------- SE block per (batch, chunk) ----------------
__global__ __launch_bounds__(256) void se_kernel(const float* __restrict__ fc1_w,
                                                 const float* __restrict__ fc1_b,
                                                 const float* __restrict__ fc2_w,
                                                 const float* __restrict__ fc2_b) {
    int b = blockIdx.y, ch = blockIdx.x;
    int tid = threadIdx.x;  // channel o
    const float* op = g_outpre + ((size_t)b * Np + (size_t)ch * 256) * COUT;
    float s = 0.f;
    for (int q = 0; q < 256; q++) s += op[(size_t)q * COUT + tid];
    __shared__ float mean[COUT];
    __shared__ float u[SEH];
    mean[tid] = s * (1.f / 256.f);
    __syncthreads();
    if (tid < SEH) {
        float acc = fc1_b[tid];
        for (int c = 0; c < COUT; c++) acc = fmaf(mean[c], fc1_w[tid * COUT + c], acc);
        u[tid] = fmaxf(acc, 0.f);
    }
    __syncthreads();
    float acc = fc2_b[tid];
#pragma unroll
    for (int j = 0; j < SEH; j++) acc = fmaf(u[j], fc2_w[tid * SEH + j], acc);
    g_se[(b * NCHUNK + ch) * COUT + tid] = 1.f / (1.f + __expf(-acc));
}

// ---------------- residual GEMM + SE-scale + combine, write (B,Cout,N) ----------------
__global__ __launch_bounds__(256) void final_kernel(const float* __restrict__ x,
                                                    float* __restrict__ out) {
    int b = blockIdx.z;
    int n0 = blockIdx.x * 128;
    int o0 = blockIdx.y * 128;
    const float* xb = x + (size_t)b * CIN * Np;
    __shared__ float As[8][128];
    __shared__ float Bs[8][128];
    float acc[8][8];
#pragma unroll
    for (int a = 0; a < 8; a++)
#pragma unroll
        for (int c = 0; c < 8; c++) acc[a][c] = 0.f;
    int tid = threadIdx.x;
    int lx = tid % 16, ly = tid / 16;  // lx -> n (fast), ly -> o
    int loadc = tid / 32, loadi = (tid % 32) * 4;
    for (int c0 = 0; c0 < CIN; c0 += 8) {
        *(float4*)&As[loadc][loadi] = *(const float4*)(xb + (size_t)(c0 + loadc) * Np + n0 + loadi);
        *(float4*)&Bs[loadc][loadi] = *(const float4*)(g_WresT + (size_t)(c0 + loadc) * COUT + o0 + loadi);
        __syncthreads();
#pragma unroll
        for (int k = 0; k < 8; k++) {
            float ar[8], br[8];
#pragma unroll
            for (int a = 0; a < 8; a++) ar[a] = As[k][lx + 16 * a];
#pragma unroll
            for (int c = 0; c < 8; c++) br[c] = Bs[k][ly + 16 * c];
#pragma unroll
            for (int a = 0; a < 8; a++)
#pragma unroll
                for (int c = 0; c < 8; c++) acc[a][c] = fmaf(ar[a], br[c], acc[a][c]);
        }
        __syncthreads();
    }
    int chunkbase = (b * NCHUNK + (n0 >> 8)) * COUT;
#pragma unroll
    for (int c = 0; c < 8; c++) {
        int o = o0 + ly + 16 * c;
        float bias = g_b3[o];
        float sev = g_se[chunkbase + o];
#pragma unroll
        for (int a = 0; a < 8; a++) {
            int n = n0 + lx + 16 * a;
            float val = acc[a][c] + bias;
            val = fmaf(g_outpre[((size_t)b * Np + n) * COUT + o], sev, val);
            out[((size_t)b * COUT + o) * Np + n] = val;
        }
    }
}

// ---------------- launch ----------------
extern "C" void kernel_launch(void* const* d_in, const int* in_sizes, int n_in,
                              void* d_out, int out_size) {
    const float* x      = (const float*)d_in[0];
    const float* W_edge = (const float*)d_in[1];
    const float* bn1_g  = (const float*)d_in[2];
    const float* bn1_b  = (const float*)d_in[3];
    const float* bn1_m  = (const float*)d_in[4];
    const float* bn1_v  = (const float*)d_in[5];
    const float* w_att  = (const float*)d_in[6];
    const float* W_fuse = (const float*)d_in[7];
    const float* bn2_g  = (const float*)d_in[8];
    const float* bn2_b  = (const float*)d_in[9];
    const float* bn2_m  = (const float*)d_in[10];
    const float* bn2_v  = (const float*)d_in[11];
    const float* fc1_w  = (const float*)d_in[12];
    const float* fc1_b  = (const float*)d_in[13];
    const float* fc2_w  = (const float*)d_in[14];
    const float* fc2_b  = (const float*)d_in[15];
    const float* W_res  = (const float*)d_in[16];
    const float* bn3_g  = (const float*)d_in[17];
    const float* bn3_b  = (const float*)d_in[18];
    const float* bn3_m  = (const float*)d_in[19];
    const float* bn3_v  = (const float*)d_in[20];
    float* out = (float*)d_out;

    prep_kernel<<<64, 256>>>(W_edge, bn1_g, bn1_b, bn1_m, bn1_v,
                             W_fuse, bn2_g, bn2_b, bn2_m, bn2_v,
                             W_res, bn3_g, bn3_b, bn3_m, bn3_v);
    sq_kernel<<<dim3(Np / 256, Bn), 256>>>(x);
    d2_kernel<<<dim3(NT * (NT + 1) / 2, Bn), 256>>>(x);
    tr_kernel<<<dim3(Np / 32, Np / 32, Bn), dim3(32, 8)>>>();
    topk_kernel<<<dim3(Np, Bn), 128>>>();
    ac_gemm<<<dim3(Np / 128, Bn, 2), 256>>>(x);
    attn_kernel<<<dim3(Np, Bn), 128>>>(w_att);
    se_kernel<<<dim3(NCHUNK, Bn), 256>>>(fc1_w, fc1_b, fc2_w, fc2_b);
    final_kernel<<<dim3(Np / 128, COUT / 128, Bn), 256>>>(x, out);
}